// round 6
// baseline (speedup 1.0000x reference)
#include <cuda_runtime.h>
#include <cstdio>

#define Bq 512
#define Wq 50
#define Tq 50
#define Hq 1024
#define Vq 1024
#define MVq 64
#define Lq 30
#define H4 4096
#define EOS_IDX 1
#define BH (Bq * Hq)
#define SMEM_BYTES 40960

// ---------------- device scratch (static, no allocation) ----------------
__device__ float g_aw[Bq * Wq];
__device__ float g_c[Bq * Hq];
__device__ float g_msg[Lq * Bq * MVq];
__device__ float g_msgmask[Lq * Bq];
__device__ float g_vec[H4];
__device__ float g_cterm[1];

__device__ float g_hist_gen[(size_t)32 * BH];    // slot0=r, slot1=enc_h, 2..31=gen h
__device__ float g_hist_menc[(size_t)31 * BH];
__device__ float g_hist_dec[(size_t)51 * BH];
__device__ float g_mx[(size_t)Lq * Bq * H4];     // menc x-term (permuted cols)
__device__ float g_dx[(size_t)Tq * Bq * H4];     // dec x-term (permuted cols)
__device__ float g_din[(size_t)Tq * Bq * Hq];    // dec inputs

// pre-converted (tf32) & gate-permuted weights
__device__ unsigned wp_set[(size_t)H4 * Hq];
__device__ unsigned wp_gen[(size_t)H4 * Hq];
__device__ unsigned wp_mench[(size_t)H4 * Hq];
__device__ unsigned wp_menci[(size_t)H4 * MVq];
__device__ unsigned wp_dech[(size_t)H4 * Hq];
__device__ unsigned wp_deci[(size_t)H4 * Hq];
__device__ unsigned wp_out[(size_t)Vq * Hq];
__device__ float bp_set[H4];
__device__ float bp_gen[H4];
__device__ float bp_menc[H4];
__device__ float bp_dec[H4];

__device__ __forceinline__ float sigf(float x) { return 1.f / (1.f + expf(-x)); }

__device__ __forceinline__ unsigned f2tf32(float x) {
    unsigned r;
    asm("cvt.rna.tf32.f32 %0, %1;" : "=r"(r) : "f"(x));
    return r;
}
__device__ __forceinline__ unsigned sptr(const void* p) {
    return (unsigned)__cvta_generic_to_shared(p);
}

// =====================================================================
// tf32 GEMM mainloop: block tile 128x128, BK=16, **512 threads**
// (16 warps, 4x4 warp grid, warp tile 32x32 = 2x4 m16n8k8 mma tiles).
// Double-buffered smem, cp.async for W (pre-converted tf32),
// reg-staged cvt for A (fp32). 4 warps per SMSP for latency hiding.
// smem layout (unsigned): As0[128*20] As1 Bs0 Bs1  (40KB)
// =====================================================================
__device__ __forceinline__ void gemm_mainloop(
    const float* __restrict__ A, const unsigned* __restrict__ W,
    int K, int bm, int bn, unsigned* smem, float acc[2][4][4])
{
    const int tid = threadIdx.x;
    const int lane = tid & 31, warp = tid >> 5;
    const int wm = warp & 3, wn = warp >> 2;
    const int gid = lane >> 2, tig = lane & 3;
    const int lr = tid >> 2;         // 0..127
    const int lc = (tid & 3) << 2;   // 0,4,8,12

    unsigned* As[2] = { smem, smem + 2560 };
    unsigned* Bs[2] = { smem + 5120, smem + 7680 };

    const float* A0 = A + (size_t)(bm + lr) * K + lc;
    const unsigned* W0 = W + (size_t)(bn + lr) * K + lc;

    // prologue: tile 0
    {
        unsigned d0 = sptr(&Bs[0][lr * 20 + lc]);
        asm volatile(
            "cp.async.cg.shared.global [%0],[%1],16;\n"
            "cp.async.commit_group;\n" :: "r"(d0), "l"(W0));
        float4 f0 = *(const float4*)A0;
        uint4 u;
        u.x = f2tf32(f0.x); u.y = f2tf32(f0.y); u.z = f2tf32(f0.z); u.w = f2tf32(f0.w);
        *(uint4*)&As[0][lr * 20 + lc] = u;
        asm volatile("cp.async.wait_group 0;\n");
        __syncthreads();
    }

    const int T = K / 16;
    for (int t = 0; t < T; t++) {
        unsigned* Ac = As[t & 1];
        unsigned* Bc = Bs[t & 1];
        unsigned* An = As[(t & 1) ^ 1];
        unsigned* Bn = Bs[(t & 1) ^ 1];
        const bool more = (t + 1 < T);
        float4 f0;
        if (more) {
            int off = (t + 1) * 16;
            unsigned d0 = sptr(&Bn[lr * 20 + lc]);
            asm volatile(
                "cp.async.cg.shared.global [%0],[%1],16;\n"
                "cp.async.commit_group;\n" :: "r"(d0), "l"(W0 + off));
            f0 = *(const float4*)(A0 + off);
        }
#pragma unroll
        for (int kk = 0; kk < 16; kk += 8) {
            unsigned a[2][4], b[4][2];
#pragma unroll
            for (int mt = 0; mt < 2; mt++) {
                int rm = wm * 32 + mt * 16 + gid;
                a[mt][0] = Ac[rm * 20 + kk + tig];
                a[mt][1] = Ac[(rm + 8) * 20 + kk + tig];
                a[mt][2] = Ac[rm * 20 + kk + tig + 4];
                a[mt][3] = Ac[(rm + 8) * 20 + kk + tig + 4];
            }
#pragma unroll
            for (int nt = 0; nt < 4; nt++) {
                int rn = wn * 32 + nt * 8 + gid;
                b[nt][0] = Bc[rn * 20 + kk + tig];
                b[nt][1] = Bc[rn * 20 + kk + tig + 4];
            }
#pragma unroll
            for (int mt = 0; mt < 2; mt++)
#pragma unroll
                for (int nt = 0; nt < 4; nt++) {
                    asm volatile(
                        "mma.sync.aligned.m16n8k8.row.col.f32.tf32.tf32.f32 "
                        "{%0,%1,%2,%3}, {%4,%5,%6,%7}, {%8,%9}, {%0,%1,%2,%3};\n"
                        : "+f"(acc[mt][nt][0]), "+f"(acc[mt][nt][1]),
                          "+f"(acc[mt][nt][2]), "+f"(acc[mt][nt][3])
                        : "r"(a[mt][0]), "r"(a[mt][1]), "r"(a[mt][2]), "r"(a[mt][3]),
                          "r"(b[nt][0]), "r"(b[nt][1]));
                }
        }
        if (more) {
            uint4 u;
            u.x = f2tf32(f0.x); u.y = f2tf32(f0.y); u.z = f2tf32(f0.z); u.w = f2tf32(f0.w);
            *(uint4*)&An[lr * 20 + lc] = u;
            asm volatile("cp.async.wait_group 0;\n");
        }
        __syncthreads();
    }
}

// ---------------- plain GEMM: C = A @ W^T + bias ------------------------------
__global__ __launch_bounds__(512, 1) void tf32_gemm_kernel(
    const float* __restrict__ A, const unsigned* __restrict__ W,
    float* __restrict__ C, int M, int N, int K, const float* __restrict__ bias)
{
    extern __shared__ unsigned smem[];
    const int bm = blockIdx.y * 128, bn = blockIdx.x * 128;
    const int lane = threadIdx.x & 31, warp = threadIdx.x >> 5;
    const int wm = warp & 3, wn = warp >> 2;
    const int gid = lane >> 2, tig = lane & 3;

    float acc[2][4][4];
#pragma unroll
    for (int i = 0; i < 2; i++)
#pragma unroll
        for (int j = 0; j < 4; j++)
#pragma unroll
            for (int q = 0; q < 4; q++) acc[i][j][q] = 0.f;

    gemm_mainloop(A, W, K, bm, bn, smem, acc);

#pragma unroll
    for (int mt = 0; mt < 2; mt++)
#pragma unroll
        for (int nt = 0; nt < 4; nt++) {
            int row = bm + wm * 32 + mt * 16 + gid;
            int col = bn + wn * 32 + nt * 8 + tig * 2;
            float bx = 0.f, by = 0.f;
            if (bias) { bx = bias[col]; by = bias[col + 1]; }
            float2 v0 = { acc[mt][nt][0] + bx, acc[mt][nt][1] + by };
            float2 v1 = { acc[mt][nt][2] + bx, acc[mt][nt][3] + by };
            *(float2*)&C[(size_t)row * N + col] = v0;
            *(float2*)&C[(size_t)(row + 8) * N + col] = v1;
        }
}

// ---------------- one fused LSTM step ----------------------------------------
// W gate-interleaved (col j = hh*4+gate), bias optional (permuted),
// xterm optional [512][4096] permuted, mask optional [512].
// Reads h from A (prev hist slot), writes h to hnext, updates c in place.
// Grid (32, 4): bn = x*128 over N=4096, bm = y*128 over M=512.
__global__ __launch_bounds__(512, 1) void step_kernel(
    const unsigned* __restrict__ W, const float* __restrict__ bias,
    const float* __restrict__ xs, const float* __restrict__ ms,
    const float* __restrict__ A, float* __restrict__ hnext,
    float* __restrict__ c)
{
    extern __shared__ unsigned smem[];
    const int bn = blockIdx.x * 128;
    const int bm = blockIdx.y * 128;
    const int tid = threadIdx.x;
    const int lane = tid & 31, warp = tid >> 5;
    const int wm = warp & 3, wn = warp >> 2;
    const int gid = lane >> 2, tig = lane & 3;
    const bool even = ((lane & 1) == 0);

    float acc[2][4][4];
#pragma unroll
    for (int i = 0; i < 2; i++)
#pragma unroll
        for (int j = 0; j < 4; j++)
#pragma unroll
            for (int q = 0; q < 4; q++) acc[i][j][q] = 0.f;

    gemm_mainloop(A, W, Hq, bm, bn, smem, acc);

    // fused LSTM epilogue
#pragma unroll
    for (int mt = 0; mt < 2; mt++)
#pragma unroll
        for (int nt = 0; nt < 4; nt++) {
            int row = bm + wm * 32 + mt * 16 + gid;
            int col = bn + wn * 32 + nt * 8 + tig * 2;
            float v0 = acc[mt][nt][0], v1 = acc[mt][nt][1];
            float v2 = acc[mt][nt][2], v3 = acc[mt][nt][3];
            if (bias) {
                float2 bb = *(const float2*)&bias[col];
                v0 += bb.x; v1 += bb.y; v2 += bb.x; v3 += bb.y;
            }
            if (xs) {
                float2 x0 = *(const float2*)&xs[(size_t)row * H4 + col];
                float2 x1 = *(const float2*)&xs[(size_t)(row + 8) * H4 + col];
                v0 += x0.x; v1 += x0.y; v2 += x1.x; v3 += x1.y;
            }
            float s0 = __shfl_xor_sync(0xffffffffu, v0, 1);
            float s1 = __shfl_xor_sync(0xffffffffu, v1, 1);
            float s2 = __shfl_xor_sync(0xffffffffu, v2, 1);
            float s3 = __shfl_xor_sync(0xffffffffu, v3, 1);
            int hh = (bn + wn * 32 + nt * 8 + (tig & 2) * 2) >> 2;
            float gi, gf, gg, go;
            int r;
            if (even) { gi = v0; gf = v1; gg = s0; go = s1; r = row; }
            else      { gi = s2; gf = s3; gg = v2; go = v3; r = row + 8; }
            size_t ci = (size_t)r * Hq + hh;
            float cold = c[ci];
            float cn = sigf(gf) * cold + sigf(gi) * tanhf(gg);
            float hn = sigf(go) * tanhf(cn);
            if (ms) {
                float mtv = ms[r];
                float hp = A[ci];
                hn = mtv * hn + (1.f - mtv) * hp;
                cn = mtv * cn + (1.f - mtv) * cold;
            }
            c[ci] = cn;
            hnext[ci] = hn;
        }
}

// ---------------- prep kernels --------------------------------------------------
// dst[j][k] = tf32(src[(gate*1024+hh)][k]), j = hh*4+gate   (N=4096 rows)
__global__ void permW_kernel(const float* __restrict__ src, unsigned* __restrict__ dst, int K)
{
    int idx = blockIdx.x * blockDim.x + threadIdx.x;
    int K4 = K >> 2;
    if (idx >= H4 * K4) return;
    int j = idx / K4, k4 = idx % K4;
    int hh = j >> 2, gate = j & 3;
    int srow = (gate << 10) + hh;
    float4 v = ((const float4*)(src + (size_t)srow * K))[k4];
    uint4 u;
    u.x = f2tf32(v.x); u.y = f2tf32(v.y); u.z = f2tf32(v.z); u.w = f2tf32(v.w);
    ((uint4*)(dst + (size_t)j * K))[k4] = u;
}

__global__ void cvtW_kernel(const float* __restrict__ src, unsigned* __restrict__ dst, int n4)
{
    int idx = blockIdx.x * blockDim.x + threadIdx.x;
    if (idx >= n4) return;
    float4 v = ((const float4*)src)[idx];
    uint4 u;
    u.x = f2tf32(v.x); u.y = f2tf32(v.y); u.z = f2tf32(v.z); u.w = f2tf32(v.w);
    ((uint4*)dst)[idx] = u;
}

__global__ void permvec_kernel(const float* __restrict__ a, const float* __restrict__ b,
                               float* __restrict__ dst)
{
    int j = blockIdx.x * blockDim.x + threadIdx.x;
    if (j >= H4) return;
    int hh = j >> 2, gate = j & 3;
    int s = (gate << 10) + hh;
    float v = a[s];
    if (b) v += b[s];
    dst[j] = v;
}

// ---------------- encoder helpers ----------------------------------------------
__global__ void cterm_kernel(const float* __restrict__ set_h0,
                             const float* __restrict__ attn_w,
                             const float* __restrict__ attn_b)
{
    __shared__ float red[256];
    float s = 0.f;
    for (int i = threadIdx.x; i < Hq; i += 256) s += set_h0[i] * attn_w[i];
    red[threadIdx.x] = s;
    __syncthreads();
    for (int st = 128; st; st >>= 1) {
        if (threadIdx.x < st) red[threadIdx.x] += red[threadIdx.x + st];
        __syncthreads();
    }
    if (threadIdx.x == 0) g_cterm[0] = red[0] + attn_b[0];
}

__global__ void aw_kernel(const int* __restrict__ input_var,
                          const float* __restrict__ input_mask,
                          const float* __restrict__ embedding,
                          const float* __restrict__ attn_w)
{
    int gw = (blockIdx.x * blockDim.x + threadIdx.x) >> 5;
    int lane = threadIdx.x & 31;
    if (gw >= Bq * Wq) return;
    int b = gw / Wq, w = gw % Wq;
    int idx = input_var[b * Wq + w];
    const float* e = embedding + (size_t)idx * Hq;
    const float* a2 = attn_w + Hq;
    float s = 0.f;
    for (int k = lane; k < Hq; k += 32) s += e[k] * a2[k];
#pragma unroll
    for (int o = 16; o; o >>= 1) s += __shfl_xor_sync(0xffffffffu, s, o);
    if (lane == 0) {
        float z = sigf(s + g_cterm[0]);
        g_aw[b * Wq + w] = z * input_mask[w * Bq + b];
    }
}

__global__ void r_kernel(const int* __restrict__ input_var,
                         const float* __restrict__ embedding,
                         float* __restrict__ out)
{
    int b = blockIdx.x;
    __shared__ float awr[Wq];
    __shared__ int idxs[Wq];
    if (threadIdx.x < Wq) {
        awr[threadIdx.x] = g_aw[b * Wq + threadIdx.x];
        idxs[threadIdx.x] = input_var[b * Wq + threadIdx.x];
    }
    __syncthreads();
    for (int h = threadIdx.x; h < Hq; h += blockDim.x) {
        float acc = 0.f;
#pragma unroll 5
        for (int w = 0; w < Wq; w++)
            acc += awr[w] * embedding[(size_t)idxs[w] * Hq + h];
        out[(size_t)b * Hq + h] = acc;
    }
}

__global__ void vecgate_kernel(const float* __restrict__ x, const float* __restrict__ Wm,
                               const float* __restrict__ b1, const float* __restrict__ b2,
                               int K)
{
    int n = (blockIdx.x * blockDim.x + threadIdx.x) >> 5;
    int lane = threadIdx.x & 31;
    if (n >= H4) return;
    float s = 0.f;
    for (int k = lane; k < K; k += 32) s += x[k] * Wm[(size_t)n * K + k];
#pragma unroll
    for (int o = 16; o; o >>= 1) s += __shfl_xor_sync(0xffffffffu, s, o);
    if (lane == 0) g_vec[n] = s + b1[n] + b2[n];
}

__global__ void bcast_kernel(float* __restrict__ dst, const float* __restrict__ src)
{
    int i = blockIdx.x * blockDim.x + threadIdx.x;
    if (i < BH) dst[i] = src[i % Hq];
}

// ---------------- batched generator head ---------------------------------------
__global__ __launch_bounds__(256) void genhead_kernel(const float* __restrict__ outW,
                                                      const float* __restrict__ outb)
{
    int l = blockIdx.y;
    int b0 = blockIdx.x * 8;
    const float* h = g_hist_gen + (size_t)(l + 2) * BH;
    __shared__ float hs[8][Hq];
    __shared__ float es[8][MVq];
    int tid = threadIdx.x;

    const float4* src = (const float4*)(h + (size_t)b0 * Hq);
    float4* dst = (float4*)&hs[0][0];
    for (int i = tid; i < 8 * Hq / 4; i += 256) dst[i] = src[i];
    __syncthreads();

    int n = tid & 63;
    int sb = tid >> 6;
    float accs[2];
#pragma unroll
    for (int rep = 0; rep < 2; rep++) {
        int bb = sb + rep * 4;
        float acc = outb[n];
        const float4* wr = (const float4*)(outW + (size_t)n * Hq);
        const float4* hv = (const float4*)&hs[bb][0];
#pragma unroll 8
        for (int kk = 0; kk < Hq / 4; kk++) {
            float4 w4 = wr[kk];
            float4 h4 = hv[kk];
            acc += w4.x * h4.x + w4.y * h4.y + w4.z * h4.z + w4.w * h4.w;
        }
        accs[rep] = acc;
        es[bb][n] = acc;
    }
    __syncthreads();
    float er[2];
#pragma unroll
    for (int rep = 0; rep < 2; rep++) {
        int bb = sb + rep * 4;
        float mx = -1e30f;
#pragma unroll
        for (int i = 0; i < MVq; i++) mx = fmaxf(mx, es[bb][i]);
        er[rep] = expf(accs[rep] - mx);
    }
    __syncthreads();
#pragma unroll
    for (int rep = 0; rep < 2; rep++) { int bb = sb + rep * 4; es[bb][n] = er[rep]; }
    __syncthreads();
#pragma unroll
    for (int rep = 0; rep < 2; rep++) {
        int bb = sb + rep * 4;
        float ssum = 0.f;
#pragma unroll
        for (int i = 0; i < MVq; i++) ssum += es[bb][i];
        int b = b0 + bb;
        g_msg[(size_t)l * Bq * MVq + b * MVq + n] = er[rep] / ssum;
    }
}

// sequential EOS-mask scan
__global__ void maskscan_kernel()
{
    int b = blockIdx.x * blockDim.x + threadIdx.x;
    if (b >= Bq) return;
    float m = 1.f;
    for (int l = 0; l < Lq; l++) {
        g_msgmask[l * Bq + b] = m;
        m *= (1.f - g_msg[((size_t)l * Bq + b) * MVq + EOS_IDX]);
    }
}

// ---------------- decoder input gather ------------------------------------------
__global__ void decin_kernel(const int* __restrict__ target_var,
                             const float* __restrict__ embedding)
{
    long i = (long)blockIdx.x * blockDim.x + threadIdx.x;
    if (i >= (long)Tq * Bq * Hq) return;
    int hh = (int)(i % Hq);
    long tb = i / Hq;
    int b = (int)(tb % Bq);
    int t = (int)(tb / Bq);
    int idx = (t == 0) ? 0 : target_var[(t - 1) * Bq + b];  // SOS_INDEX = 0
    g_din[i] = embedding[(size_t)idx * Hq + hh];
}

// ---------------- host orchestration --------------------------------------------
extern "C" void kernel_launch(void* const* d_in, const int* in_sizes, int n_in,
                              void* d_out, int out_size)
{
    int k = 0;
    const int*   input_var  = (const int*)d_in[k++];
    const float* input_mask = (const float*)d_in[k++];
    const int*   target_var = (const int*)d_in[k++];
    if (n_in >= 32) k++;  // skip target_max_len scalar if present
    const float* embedding = (const float*)d_in[k++];
    const float* attn_w    = (const float*)d_in[k++];
    const float* attn_b    = (const float*)d_in[k++];
    const float* set_Wih   = (const float*)d_in[k++];
    const float* set_Whh   = (const float*)d_in[k++];
    const float* set_bih   = (const float*)d_in[k++];
    const float* set_bhh   = (const float*)d_in[k++];
    const float* set_h0    = (const float*)d_in[k++];
    const float* set_c0    = (const float*)d_in[k++];
    const float* gen_x0    = (const float*)d_in[k++];
    const float* gen_Wih   = (const float*)d_in[k++];
    const float* gen_Whh   = (const float*)d_in[k++];
    const float* gen_bih   = (const float*)d_in[k++];
    const float* gen_bhh   = (const float*)d_in[k++];
    const float* gen_outW  = (const float*)d_in[k++];
    const float* gen_outb  = (const float*)d_in[k++];
    const float* menc_Wih  = (const float*)d_in[k++];
    const float* menc_Whh  = (const float*)d_in[k++];
    const float* menc_bih  = (const float*)d_in[k++];
    const float* menc_bhh  = (const float*)d_in[k++];
    const float* menc_h0   = (const float*)d_in[k++];
    const float* menc_c0   = (const float*)d_in[k++];
    const float* dec_Wih   = (const float*)d_in[k++];
    const float* dec_Whh   = (const float*)d_in[k++];
    const float* dec_bih   = (const float*)d_in[k++];
    const float* dec_bhh   = (const float*)d_in[k++];
    const float* dec_outW  = (const float*)d_in[k++];
    const float* dec_outb  = (const float*)d_in[k++];
    float* out = (float*)d_out;

    float *p_c, *p_vec, *p_hg, *p_hm, *p_hd, *p_mx, *p_dx, *p_di, *p_msg, *p_mm;
    float *p_bset, *p_bgen, *p_bmenc, *p_bdec;
    unsigned *p_wset, *p_wgen, *p_wmench, *p_wmenci, *p_wdech, *p_wdeci, *p_wout;
    cudaGetSymbolAddress((void**)&p_c,     g_c);
    cudaGetSymbolAddress((void**)&p_vec,   g_vec);
    cudaGetSymbolAddress((void**)&p_hg,    g_hist_gen);
    cudaGetSymbolAddress((void**)&p_hm,    g_hist_menc);
    cudaGetSymbolAddress((void**)&p_hd,    g_hist_dec);
    cudaGetSymbolAddress((void**)&p_mx,    g_mx);
    cudaGetSymbolAddress((void**)&p_dx,    g_dx);
    cudaGetSymbolAddress((void**)&p_di,    g_din);
    cudaGetSymbolAddress((void**)&p_msg,   g_msg);
    cudaGetSymbolAddress((void**)&p_mm,    g_msgmask);
    cudaGetSymbolAddress((void**)&p_bset,  bp_set);
    cudaGetSymbolAddress((void**)&p_bgen,  bp_gen);
    cudaGetSymbolAddress((void**)&p_bmenc, bp_menc);
    cudaGetSymbolAddress((void**)&p_bdec,  bp_dec);
    cudaGetSymbolAddress((void**)&p_wset,  wp_set);
    cudaGetSymbolAddress((void**)&p_wgen,  wp_gen);
    cudaGetSymbolAddress((void**)&p_wmench, wp_mench);
    cudaGetSymbolAddress((void**)&p_wmenci, wp_menci);
    cudaGetSymbolAddress((void**)&p_wdech, wp_dech);
    cudaGetSymbolAddress((void**)&p_wdeci, wp_deci);
    cudaGetSymbolAddress((void**)&p_wout,  wp_out);

    const int PW1024 = (H4 * (Hq / 4) + 255) / 256;
    const int PW64   = (H4 * (MVq / 4) + 255) / 256;
    const dim3 SG(32, 4);   // step kernel grid: N=4096/128 x M=512/128

    // ---- weight prep (permute + tf32 convert) ----
    permW_kernel<<<PW1024, 256>>>(set_Wih,  p_wset,  Hq);
    permW_kernel<<<PW1024, 256>>>(gen_Whh,  p_wgen,  Hq);
    permW_kernel<<<PW1024, 256>>>(menc_Whh, p_wmench, Hq);
    permW_kernel<<<PW64,   256>>>(menc_Wih, p_wmenci, MVq);
    permW_kernel<<<PW1024, 256>>>(dec_Whh,  p_wdech, Hq);
    permW_kernel<<<PW1024, 256>>>(dec_Wih,  p_wdeci, Hq);
    cvtW_kernel<<<(Vq * Hq / 4 + 255) / 256, 256>>>(dec_outW, p_wout, Vq * Hq / 4);
    permvec_kernel<<<(H4 + 255) / 256, 256>>>(menc_bih, menc_bhh, p_bmenc);
    permvec_kernel<<<(H4 + 255) / 256, 256>>>(dec_bih, dec_bhh, p_bdec);

    // ---- encoder: attention + 1 fused LSTM step ----
    cterm_kernel<<<1, 256>>>(set_h0, attn_w, attn_b);
    aw_kernel<<<(Bq * Wq * 32 + 255) / 256, 256>>>(input_var, input_mask, embedding, attn_w);
    r_kernel<<<Bq, 256>>>(input_var, embedding, p_hg);  // hist_gen slot0 = r
    vecgate_kernel<<<(H4 * 32 + 255) / 256, 256>>>(set_h0, set_Whh, set_bih, set_bhh, Hq);
    permvec_kernel<<<(H4 + 255) / 256, 256>>>(p_vec, nullptr, p_bset);
    bcast_kernel<<<(BH + 255) / 256, 256>>>(p_c, set_c0);
    step_kernel<<<SG, 512, SMEM_BYTES>>>(p_wset, p_bset, nullptr, nullptr,
                                         p_hg, p_hg + BH, p_c);

    // ---- generator scan ----
    vecgate_kernel<<<(H4 * 32 + 255) / 256, 256>>>(gen_x0, gen_Wih, gen_bih, gen_bhh, MVq);
    permvec_kernel<<<(H4 + 255) / 256, 256>>>(p_vec, nullptr, p_bgen);
    for (int l = 0; l < Lq; l++)
        step_kernel<<<SG, 512, SMEM_BYTES>>>(p_wgen, p_bgen, nullptr, nullptr,
                                             p_hg + (size_t)(1 + l) * BH,
                                             p_hg + (size_t)(2 + l) * BH, p_c);

    // ---- batched generator head + mask scan ----
    genhead_kernel<<<dim3(Bq / 8, Lq), 256>>>(gen_outW, gen_outb);
    maskscan_kernel<<<2, 256>>>();

    // ---- message encoder ----
    tf32_gemm_kernel<<<dim3(H4 / 128, Lq * Bq / 128), 512, SMEM_BYTES>>>(
        p_msg, p_wmenci, p_mx, Lq * Bq, H4, MVq, p_bmenc);
    bcast_kernel<<<(BH + 255) / 256, 256>>>(p_hm, menc_h0);
    bcast_kernel<<<(BH + 255) / 256, 256>>>(p_c, menc_c0);
    for (int l = 0; l < Lq; l++)
        step_kernel<<<SG, 512, SMEM_BYTES>>>(p_wmench, nullptr,
                                             p_mx + (size_t)l * Bq * H4,
                                             p_mm + (size_t)l * Bq,
                                             p_hm + (size_t)l * BH,
                                             p_hm + (size_t)(l + 1) * BH, p_c);

    // ---- decoder ----
    decin_kernel<<<(int)(((long)Tq * Bq * Hq + 255) / 256), 256>>>(target_var, embedding);
    tf32_gemm_kernel<<<dim3(H4 / 128, Tq * Bq / 128), 512, SMEM_BYTES>>>(
        p_di, p_wdeci, p_dx, Tq * Bq, H4, Hq, p_bdec);
    cudaMemcpyAsync(p_hd, p_hm + (size_t)Lq * BH, (size_t)BH * 4,
                    cudaMemcpyDeviceToDevice);
    for (int t = 0; t < Tq; t++)
        step_kernel<<<SG, 512, SMEM_BYTES>>>(p_wdech, nullptr,
                                             p_dx + (size_t)t * Bq * H4, nullptr,
                                             p_hd + (size_t)t * BH,
                                             p_hd + (size_t)(t + 1) * BH, p_c);

    // ---- final logits: one big GEMM over h history ----
    tf32_gemm_kernel<<<dim3(Vq / 128, Tq * Bq / 128), 512, SMEM_BYTES>>>(
        p_hd + BH, p_wout, out, Tq * Bq, Vq, Hq, dec_outb);
}

// round 9
// speedup vs baseline: 1.3096x; 1.3096x over previous
#include <cuda_runtime.h>
#include <cuda_fp16.h>
#include <cstdio>

#define Bq 512
#define Wq 50
#define Tq 50
#define Hq 1024
#define Vq 1024
#define MVq 64
#define Lq 30
#define H4 4096
#define EOS_IDX 1

// ---------------- device scratch (static, no allocation) ----------------
__device__ float g_aw[Bq * Wq];
__device__ float g_r[Bq * Hq];
__device__ float g_h[Bq * Hq];
__device__ float g_c[Bq * Hq];
__device__ float g_g[Bq * H4];
__device__ float g_msg[Lq * Bq * MVq];
__device__ float g_msgmask[Lq * Bq];
__device__ float g_m[Bq];
__device__ float g_vec[H4];
__device__ float g_cterm[1];
__device__ float g_menc_xterm[(size_t)Lq * Bq * H4];   // 251 MB
__device__ float g_dec_xterm[(size_t)Tq * Bq * H4];    // 419 MB
__device__ float g_dec_in[(size_t)Tq * Bq * Hq];       // 105 MB
__device__ float g_decb[H4 + Vq];

// packed half2 weights (uint = 2 halfs along K)
__device__ unsigned wh_set[(size_t)H4 * Hq / 2];
__device__ unsigned wh_gen[(size_t)H4 * Hq / 2];
__device__ unsigned wh_mench[(size_t)H4 * Hq / 2];
__device__ unsigned wh_menci[(size_t)H4 * MVq / 2];
__device__ unsigned wh_deci[(size_t)H4 * Hq / 2];
__device__ unsigned wh_comb[(size_t)(H4 + Vq) * Hq / 2];   // [dec_Whh ; dec_outW]

__device__ __forceinline__ float sigf(float x) { return 1.f / (1.f + expf(-x)); }

__device__ __forceinline__ unsigned packh2(float x, float y) {
    __half2 h = __floats2half2_rn(x, y);
    return *(unsigned*)&h;
}

// =====================================================================
// FP16 tensor-core GEMM: C = A(MxK,fp32) @ Wh(NxK,half)^T [+bias] [+addM]
// Output split: col < colSplit -> C (ld ldC); else -> C2 (ld ldC2).
// Block tile 128x128, K-tile 16, 256 threads (8 warps, 4x2 warp grid,
// warp tile 32x64 = 2x8 m16n8k16 mma tiles).
// Requires: M%128==0, N%128==0, K%16==0, colSplit & addN even.
// =====================================================================
__global__ __launch_bounds__(256, 2) void mma_gemm_kernel(
    const float* __restrict__ A, const unsigned* __restrict__ Wh,
    float* __restrict__ C, float* __restrict__ C2,
    int M, int N, int K,
    const float* __restrict__ bias, const float* __restrict__ addM,
    int addN, int colSplit, int ldC, int ldC2)
{
    __shared__ unsigned As[128][9];  // [m][k-pair], stride 9 -> conflict-free frags
    __shared__ unsigned Bs[128][9];  // [n][k-pair]

    const int tid  = threadIdx.x;
    const int lane = tid & 31;
    const int warp = tid >> 5;
    const int wm   = warp & 3;    // warp m offset = wm*32
    const int wn   = warp >> 2;   // warp n offset = wn*64
    const int gid  = lane >> 2;
    const int tig  = lane & 3;

    const int bm = blockIdx.y * 128;
    const int bn = blockIdx.x * 128;

    // A: 128x16 fp32 tile, thread handles rows lrA, lrA+64, 4 floats each
    const int lrA = tid >> 2;            // 0..63
    const int lcA = (tid & 3) << 2;      // float col: 0,4,8,12
    // W: 128x8(uint) tile, thread handles row lrW, 4 uints
    const int lrW = tid >> 1;            // 0..127
    const int lcW = (tid & 1) << 2;      // uint col: 0,4

    const int K2 = K >> 1;
    const float* Ag0 = A + (size_t)(bm + lrA) * K + lcA;
    const float* Ag1 = A + (size_t)(bm + lrA + 64) * K + lcA;
    const unsigned* Wg = Wh + (size_t)(bn + lrW) * K2 + lcW;

    float4 fa0 = *(const float4*)Ag0;
    float4 fa1 = *(const float4*)Ag1;
    uint4  fw  = *(const uint4*)Wg;

    float c[2][8][4];
#pragma unroll
    for (int i = 0; i < 2; i++)
#pragma unroll
        for (int j = 0; j < 8; j++)
#pragma unroll
            for (int q = 0; q < 4; q++) c[i][j][q] = 0.f;

    for (int k0 = 0; k0 < K; k0 += 16) {
        if (k0) __syncthreads();  // previous compute finished before overwrite
        {
            int ca = lcA >> 1;
            As[lrA][ca]          = packh2(fa0.x, fa0.y);
            As[lrA][ca + 1]      = packh2(fa0.z, fa0.w);
            As[lrA + 64][ca]     = packh2(fa1.x, fa1.y);
            As[lrA + 64][ca + 1] = packh2(fa1.z, fa1.w);
            Bs[lrW][lcW]     = fw.x;
            Bs[lrW][lcW + 1] = fw.y;
            Bs[lrW][lcW + 2] = fw.z;
            Bs[lrW][lcW + 3] = fw.w;
        }
        __syncthreads();

        if (k0 + 16 < K) {  // prefetch next K-tile (overlaps with compute below)
            fa0 = *(const float4*)(Ag0 + k0 + 16);
            fa1 = *(const float4*)(Ag1 + k0 + 16);
            fw  = *(const uint4*)(Wg + ((k0 + 16) >> 1));
        }

        {
            unsigned a[2][4], b[8][2];
#pragma unroll
            for (int mt = 0; mt < 2; mt++) {
                int rm = wm * 32 + mt * 16 + gid;
                a[mt][0] = As[rm][tig];
                a[mt][1] = As[rm + 8][tig];
                a[mt][2] = As[rm][tig + 4];
                a[mt][3] = As[rm + 8][tig + 4];
            }
#pragma unroll
            for (int nt = 0; nt < 8; nt++) {
                int rn = wn * 64 + nt * 8 + gid;
                b[nt][0] = Bs[rn][tig];
                b[nt][1] = Bs[rn][tig + 4];
            }
#pragma unroll
            for (int mt = 0; mt < 2; mt++)
#pragma unroll
                for (int nt = 0; nt < 8; nt++) {
                    asm volatile(
                        "mma.sync.aligned.m16n8k16.row.col.f32.f16.f16.f32 "
                        "{%0,%1,%2,%3}, {%4,%5,%6,%7}, {%8,%9}, {%0,%1,%2,%3};\n"
                        : "+f"(c[mt][nt][0]), "+f"(c[mt][nt][1]),
                          "+f"(c[mt][nt][2]), "+f"(c[mt][nt][3])
                        : "r"(a[mt][0]), "r"(a[mt][1]), "r"(a[mt][2]), "r"(a[mt][3]),
                          "r"(b[nt][0]), "r"(b[nt][1]));
                }
        }
    }

    // ---------------- epilogue ----------------
#pragma unroll
    for (int mt = 0; mt < 2; mt++) {
#pragma unroll
        for (int nt = 0; nt < 8; nt++) {
            int row = bm + wm * 32 + mt * 16 + gid;
            int col = bn + wn * 64 + nt * 8 + tig * 2;
#pragma unroll
            for (int half = 0; half < 2; half++) {
                int r = row + half * 8;
                float2 v;
                v.x = c[mt][nt][half * 2];
                v.y = c[mt][nt][half * 2 + 1];
                if (bias) { v.x += bias[col]; v.y += bias[col + 1]; }
                if (addM && col < addN) {
                    float2 m = *(const float2*)&addM[(size_t)r * addN + col];
                    v.x += m.x; v.y += m.y;
                }
                if (col < colSplit)
                    *(float2*)&C[(size_t)r * ldC + col] = v;
                else
                    *(float2*)&C2[(size_t)r * ldC2 + (col - colSplit)] = v;
            }
        }
    }
}

// ---------------- weight convert: fp32 -> packed half2 ---------------------------
__global__ void cvtWh_kernel(const float* __restrict__ src, unsigned* __restrict__ dst,
                             long n2)
{
    long i = (long)blockIdx.x * blockDim.x + threadIdx.x;
    if (i >= n2) return;
    dst[i] = packh2(src[2 * i], src[2 * i + 1]);
}

// ---------------- attention const term ------------------------------------------------
__global__ void cterm_kernel(const float* __restrict__ set_h0,
                             const float* __restrict__ attn_w,
                             const float* __restrict__ attn_b)
{
    __shared__ float red[256];
    float s = 0.f;
    for (int i = threadIdx.x; i < Hq; i += 256) s += set_h0[i] * attn_w[i];
    red[threadIdx.x] = s;
    __syncthreads();
    for (int st = 128; st; st >>= 1) {
        if (threadIdx.x < st) red[threadIdx.x] += red[threadIdx.x + st];
        __syncthreads();
    }
    if (threadIdx.x == 0) g_cterm[0] = red[0] + attn_b[0];
}

// ---------------- attention weights aw[b,w] -------------------------------------------
__global__ void aw_kernel(const int* __restrict__ input_var,
                          const float* __restrict__ input_mask,
                          const float* __restrict__ embedding,
                          const float* __restrict__ attn_w)
{
    int gw = (blockIdx.x * blockDim.x + threadIdx.x) >> 5;
    int lane = threadIdx.x & 31;
    if (gw >= Bq * Wq) return;
    int b = gw / Wq, w = gw % Wq;
    int idx = input_var[b * Wq + w];
    const float* e = embedding + (size_t)idx * Hq;
    const float* a2 = attn_w + Hq;
    float s = 0.f;
    for (int k = lane; k < Hq; k += 32) s += e[k] * a2[k];
#pragma unroll
    for (int o = 16; o; o >>= 1) s += __shfl_xor_sync(0xffffffffu, s, o);
    if (lane == 0) {
        float z = sigf(s + g_cterm[0]);
        g_aw[b * Wq + w] = z * input_mask[w * Bq + b];
    }
}

// ---------------- r[b,h] = sum_w aw[b,w] * embedding[iv[b,w], h] -----------------------
__global__ void r_kernel(const int* __restrict__ input_var,
                         const float* __restrict__ embedding)
{
    int b = blockIdx.x;
    __shared__ float awr[Wq];
    __shared__ int idxs[Wq];
    if (threadIdx.x < Wq) {
        awr[threadIdx.x] = g_aw[b * Wq + threadIdx.x];
        idxs[threadIdx.x] = input_var[b * Wq + threadIdx.x];
    }
    __syncthreads();
    for (int h = threadIdx.x; h < Hq; h += blockDim.x) {
        float acc = 0.f;
#pragma unroll 5
        for (int w = 0; w < Wq; w++)
            acc += awr[w] * embedding[(size_t)idxs[w] * Hq + h];
        g_r[b * Hq + h] = acc;
    }
}

// ---------------- out[n] = b1[n]+b2[n]+dot(x[K], Wm[n,:]) -------------------------------
__global__ void vecgate_kernel(const float* __restrict__ x, const float* __restrict__ Wm,
                               const float* __restrict__ b1, const float* __restrict__ b2,
                               int K)
{
    int n = (blockIdx.x * blockDim.x + threadIdx.x) >> 5;
    int lane = threadIdx.x & 31;
    if (n >= H4) return;
    float s = 0.f;
    for (int k = lane; k < K; k += 32) s += x[k] * Wm[(size_t)n * K + k];
#pragma unroll
    for (int o = 16; o; o >>= 1) s += __shfl_xor_sync(0xffffffffu, s, o);
    if (lane == 0) g_vec[n] = s + b1[n] + b2[n];
}

// ---------------- broadcast row src[H] into dst[B,H] -----------------------------------
__global__ void bcast_kernel(float* __restrict__ dst, const float* __restrict__ src)
{
    int i = blockIdx.x * blockDim.x + threadIdx.x;
    if (i < Bq * Hq) dst[i] = src[i % Hq];
}

__global__ void ones_kernel()
{
    int i = blockIdx.x * blockDim.x + threadIdx.x;
    if (i < Bq) g_m[i] = 1.f;
}

// ---------------- LSTM pointwise ------------------------------------------------------
__global__ void lstm_pw_kernel(float* __restrict__ h, float* __restrict__ c,
                               const float* __restrict__ mask)
{
    int i = blockIdx.x * blockDim.x + threadIdx.x;
    if (i >= Bq * Hq) return;
    int b = i / Hq, hh = i % Hq;
    const float* gr = g_g + (size_t)b * H4;
    float gi = gr[hh], gf = gr[Hq + hh], gg = gr[2 * Hq + hh], go = gr[3 * Hq + hh];
    float co = c[i];
    float cn = sigf(gf) * co + sigf(gi) * tanhf(gg);
    float hn = sigf(go) * tanhf(cn);
    if (mask) {
        float mt = mask[b];
        float ho = h[i];
        hn = mt * hn + (1.f - mt) * ho;
        cn = mt * cn + (1.f - mt) * co;
    }
    h[i] = hn;
    c[i] = cn;
}

// ---------------- generator head: 8 batches per block, outW reused ---------------------
__global__ __launch_bounds__(256) void gen_out_kernel(const float* __restrict__ outW,
                                                      const float* __restrict__ outb, int l)
{
    int b0 = blockIdx.x * 8;
    __shared__ float hs[8][Hq];
    __shared__ float es[8][MVq];
    int tid = threadIdx.x;

    const float4* src = (const float4*)(g_h + (size_t)b0 * Hq);
    float4* dst = (float4*)&hs[0][0];
    for (int i = tid; i < 8 * Hq / 4; i += 256) dst[i] = src[i];
    __syncthreads();

    int n = tid & 63;
    int sb = tid >> 6;  // 0..3
    float accs[2];
#pragma unroll
    for (int rep = 0; rep < 2; rep++) {
        int bb = sb + rep * 4;
        float acc = outb[n];
        const float4* wr = (const float4*)(outW + (size_t)n * Hq);
        const float4* hv = (const float4*)&hs[bb][0];
#pragma unroll 8
        for (int kk = 0; kk < Hq / 4; kk++) {
            float4 w4 = wr[kk];
            float4 h4 = hv[kk];
            acc += w4.x * h4.x + w4.y * h4.y + w4.z * h4.z + w4.w * h4.w;
        }
        accs[rep] = acc;
        es[bb][n] = acc;
    }
    __syncthreads();

    float er[2];
#pragma unroll
    for (int rep = 0; rep < 2; rep++) {
        int bb = sb + rep * 4;
        float mx = -1e30f;
#pragma unroll
        for (int i = 0; i < MVq; i++) mx = fmaxf(mx, es[bb][i]);
        er[rep] = expf(accs[rep] - mx);
    }
    __syncthreads();
#pragma unroll
    for (int rep = 0; rep < 2; rep++) { int bb = sb + rep * 4; es[bb][n] = er[rep]; }
    __syncthreads();
#pragma unroll
    for (int rep = 0; rep < 2; rep++) {
        int bb = sb + rep * 4;
        float ssum = 0.f;
#pragma unroll
        for (int i = 0; i < MVq; i++) ssum += es[bb][i];
        float p = er[rep] / ssum;
        int b = b0 + bb;
        g_msg[(size_t)l * Bq * MVq + b * MVq + n] = p;
        if (n == EOS_IDX) {
            float mo = g_m[b];
            g_msgmask[l * Bq + b] = mo;
            g_m[b] = mo * (1.f - p);
        }
    }
}

// ---------------- decoder input gather --------------------------------------------------
__global__ void decin_kernel(const int* __restrict__ target_var,
                             const float* __restrict__ embedding)
{
    long i = (long)blockIdx.x * blockDim.x + threadIdx.x;
    if (i >= (long)Tq * Bq * Hq) return;
    int hh = (int)(i % Hq);
    long tb = i / Hq;
    int b = (int)(tb % Bq);
    int t = (int)(tb / Bq);
    int idx = (t == 0) ? 0 : target_var[(t - 1) * Bq + b];  // SOS_INDEX = 0
    g_dec_in[i] = embedding[(size_t)idx * Hq + hh];
}

// ---------------- host orchestration ----------------------------------------------------
static inline void launch_mma(const float* A, const unsigned* Wh, float* C,
                              int M, int N, int K,
                              const float* bias, const float* addM, int addN,
                              float* C2 = nullptr, int colSplit = -1,
                              int ldC = -1, int ldC2 = 0)
{
    if (colSplit < 0) colSplit = N;
    if (ldC < 0) ldC = (colSplit < N) ? colSplit : N;
    dim3 grid(N / 128, M / 128);
    mma_gemm_kernel<<<grid, 256>>>(A, Wh, C, C2, M, N, K, bias, addM, addN,
                                   colSplit, ldC, ldC2);
}

extern "C" void kernel_launch(void* const* d_in, const int* in_sizes, int n_in,
                              void* d_out, int out_size)
{
    int k = 0;
    const int*   input_var  = (const int*)d_in[k++];
    const float* input_mask = (const float*)d_in[k++];
    const int*   target_var = (const int*)d_in[k++];
    if (n_in >= 32) k++;  // skip target_max_len scalar if present
    const float* embedding = (const float*)d_in[k++];
    const float* attn_w    = (const float*)d_in[k++];
    const float* attn_b    = (const float*)d_in[k++];
    const float* set_Wih   = (const float*)d_in[k++];
    const float* set_Whh   = (const float*)d_in[k++];
    const float* set_bih   = (const float*)d_in[k++];
    const float* set_bhh   = (const float*)d_in[k++];
    const float* set_h0    = (const float*)d_in[k++];
    const float* set_c0    = (const float*)d_in[k++];
    const float* gen_x0    = (const float*)d_in[k++];
    const float* gen_Wih   = (const float*)d_in[k++];
    const float* gen_Whh   = (const float*)d_in[k++];
    const float* gen_bih   = (const float*)d_in[k++];
    const float* gen_bhh   = (const float*)d_in[k++];
    const float* gen_outW  = (const float*)d_in[k++];
    const float* gen_outb  = (const float*)d_in[k++];
    const float* menc_Wih  = (const float*)d_in[k++];
    const float* menc_Whh  = (const float*)d_in[k++];
    const float* menc_bih  = (const float*)d_in[k++];
    const float* menc_bhh  = (const float*)d_in[k++];
    const float* menc_h0   = (const float*)d_in[k++];
    const float* menc_c0   = (const float*)d_in[k++];
    const float* dec_Wih   = (const float*)d_in[k++];
    const float* dec_Whh   = (const float*)d_in[k++];
    const float* dec_bih   = (const float*)d_in[k++];
    const float* dec_bhh   = (const float*)d_in[k++];
    const float* dec_outW  = (const float*)d_in[k++];
    const float* dec_outb  = (const float*)d_in[k++];
    float* out = (float*)d_out;

    float *p_r, *p_h, *p_c, *p_g, *p_msg, *p_mm, *p_vec, *p_mx, *p_dx, *p_di, *p_db;
    unsigned *p_whset, *p_whgen, *p_whmench, *p_whmenci, *p_whdeci, *p_whcomb;
    cudaGetSymbolAddress((void**)&p_r,   g_r);
    cudaGetSymbolAddress((void**)&p_h,   g_h);
    cudaGetSymbolAddress((void**)&p_c,   g_c);
    cudaGetSymbolAddress((void**)&p_g,   g_g);
    cudaGetSymbolAddress((void**)&p_msg, g_msg);
    cudaGetSymbolAddress((void**)&p_mm,  g_msgmask);
    cudaGetSymbolAddress((void**)&p_vec, g_vec);
    cudaGetSymbolAddress((void**)&p_mx,  g_menc_xterm);
    cudaGetSymbolAddress((void**)&p_dx,  g_dec_xterm);
    cudaGetSymbolAddress((void**)&p_di,  g_dec_in);
    cudaGetSymbolAddress((void**)&p_db,  g_decb);
    cudaGetSymbolAddress((void**)&p_whset,   wh_set);
    cudaGetSymbolAddress((void**)&p_whgen,   wh_gen);
    cudaGetSymbolAddress((void**)&p_whmench, wh_mench);
    cudaGetSymbolAddress((void**)&p_whmenci, wh_menci);
    cudaGetSymbolAddress((void**)&p_whdeci,  wh_deci);
    cudaGetSymbolAddress((void**)&p_whcomb,  wh_comb);

    const int BH = Bq * Hq;
    const long NW = (long)H4 * Hq / 2;      // 2M uints for 4096x1024 weights

    // ---- weight convert to packed half2 ----
    cvtWh_kernel<<<(int)((NW + 255) / 256), 256>>>(set_Wih,  p_whset,   NW);
    cvtWh_kernel<<<(int)((NW + 255) / 256), 256>>>(gen_Whh,  p_whgen,   NW);
    cvtWh_kernel<<<(int)((NW + 255) / 256), 256>>>(menc_Whh, p_whmench, NW);
    cvtWh_kernel<<<(int)((H4 * MVq / 2 + 255) / 256), 256>>>(menc_Wih, p_whmenci,
                                                             (long)H4 * MVq / 2);
    cvtWh_kernel<<<(int)((NW + 255) / 256), 256>>>(dec_Wih,  p_whdeci,  NW);
    cvtWh_kernel<<<(int)((NW + 255) / 256), 256>>>(dec_Whh,  p_whcomb,  NW);
    cvtWh_kernel<<<(int)(((long)Vq * Hq / 2 + 255) / 256), 256>>>(
        dec_outW, p_whcomb + NW, (long)Vq * Hq / 2);
    cudaMemcpyAsync(p_db, dec_bhh, H4 * 4, cudaMemcpyDeviceToDevice);
    cudaMemcpyAsync(p_db + H4, dec_outb, Vq * 4, cudaMemcpyDeviceToDevice);

    // ===== encoder (set attention + 1 LSTM cell) =====
    cterm_kernel<<<1, 256>>>(set_h0, attn_w, attn_b);
    aw_kernel<<<(Bq * Wq * 32 + 255) / 256, 256>>>(input_var, input_mask, embedding, attn_w);
    r_kernel<<<Bq, 256>>>(input_var, embedding);
    vecgate_kernel<<<(H4 * 32 + 255) / 256, 256>>>(set_h0, set_Whh, set_bih, set_bhh, Hq);
    launch_mma(p_r, p_whset, p_g, Bq, H4, Hq, p_vec, nullptr, 0);
    bcast_kernel<<<(BH + 255) / 256, 256>>>(p_c, set_c0);
    lstm_pw_kernel<<<(BH + 255) / 256, 256>>>(p_h, p_c, nullptr);

    // ===== generator scan (L steps) =====
    vecgate_kernel<<<(H4 * 32 + 255) / 256, 256>>>(gen_x0, gen_Wih, gen_bih, gen_bhh, MVq);
    ones_kernel<<<(Bq + 255) / 256, 256>>>();
    for (int l = 0; l < Lq; l++) {
        launch_mma(p_h, p_whgen, p_g, Bq, H4, Hq, p_vec, nullptr, 0);
        lstm_pw_kernel<<<(BH + 255) / 256, 256>>>(p_h, p_c, nullptr);
        gen_out_kernel<<<Bq / 8, 256>>>(gen_outW, gen_outb, l);
    }

    // ===== message encoder: hoisted x-term GEMM, then masked scan =====
    launch_mma(p_msg, p_whmenci, p_mx, Lq * Bq, H4, MVq, menc_bih, nullptr, 0);
    bcast_kernel<<<(BH + 255) / 256, 256>>>(p_h, menc_h0);
    bcast_kernel<<<(BH + 255) / 256, 256>>>(p_c, menc_c0);
    for (int l = 0; l < Lq; l++) {
        launch_mma(p_h, p_whmench, p_g, Bq, H4, Hq, menc_bhh,
                   p_mx + (size_t)l * Bq * H4, H4);
        lstm_pw_kernel<<<(BH + 255) / 256, 256>>>(p_h, p_c, p_mm + (size_t)l * Bq);
    }

    // ===== decoder =====
    decin_kernel<<<(int)(((long)Tq * Bq * Hq + 255) / 256), 256>>>(target_var, embedding);
    launch_mma(p_di, p_whdeci, p_dx, Tq * Bq, H4, Hq, dec_bih, nullptr, 0);

    // t=0: plain recurrent gemm (no logits yet)
    launch_mma(p_h, p_whcomb, p_g, Bq, H4, Hq, dec_bhh, p_dx, H4);
    lstm_pw_kernel<<<(BH + 255) / 256, 256>>>(p_h, p_c, nullptr);
    // t=1..49: combined [Whh | outW] gemm -> g_t and logits_{t-1}
    for (int t = 1; t < Tq; t++) {
        launch_mma(p_h, p_whcomb, p_g, Bq, H4 + Vq, Hq, p_db,
                   p_dx + (size_t)t * Bq * H4, H4,
                   out + (size_t)(t - 1) * Bq * Vq, H4, H4, Vq);
        lstm_pw_kernel<<<(BH + 255) / 256, 256>>>(p_h, p_c, nullptr);
    }
    // final logits_{T-1}
    launch_mma(p_h, p_whcomb + NW, out + (size_t)(Tq - 1) * Bq * Vq, Bq, Vq, Hq,
               dec_outb, nullptr, 0);
}